// round 2
// baseline (speedup 1.0000x reference)
#include <cuda_runtime.h>

#define NPTS  50000
#define BATCH 8
#define PTILE 64
#define NTILES_PER_B ((NPTS + PTILE - 1) / PTILE)   /* 782 */
#define NTILES (BATCH * NTILES_PER_B)               /* 6256 */
#define THREADS 256
#define STR  68     /* z row stride (floats), 272B = multiple of 16B */
#define WPAD 132    /* transposed-weight row stride (floats) */

/* SMEM layout offsets in floats */
#define OFF_H2T   0
#define OFF_G2T   16896
#define OFF_Z1    33792
#define OFF_Z2    42496
#define OFF_H1W   51200
#define OFF_G1W   51712
#define OFF_H1B   52224
#define OFF_G1B   52352
#define OFF_H2B   52480
#define OFF_G2B   52608
#define OFF_OUTW  52736
#define OFF_OUTB  53120
#define OFF_X0    53124
#define OFF_XC    53316
#define OFF_K1    53508
#define OFF_K2    53700
#define OFF_KS    53892
#define SMEM_FLOATS 54084
#define SMEM_BYTES (SMEM_FLOATS * 4)

/* pre-transposed h2_w / g2_w live here: [i*WPAD + o], h2 then g2 */
__device__ float d_wT[2 * 128 * WPAD];

__global__ void wtrans_kernel(const float* __restrict__ h2w,
                              const float* __restrict__ g2w)
{
    int j = blockIdx.x * blockDim.x + threadIdx.x;
    if (j < 128 * 128) {
        int o = j >> 7, i = j & 127;
        d_wT[i * WPAD + o]              = h2w[j];
        d_wT[16896 + i * WPAD + o]      = g2w[j];
    }
}

__device__ __forceinline__ void fma2(unsigned long long &acc,
                                     unsigned long long a,
                                     unsigned long long b)
{
    asm("fma.rn.f32x2 %0, %1, %2, %0;" : "+l"(acc) : "l"(a), "l"(b));
}
__device__ __forceinline__ unsigned long long dupf(float x)
{
    unsigned long long r;
    asm("mov.b64 %0, {%1, %1};" : "=l"(r) : "f"(x));
    return r;
}
__device__ __forceinline__ float2 unpk(unsigned long long v)
{
    float2 r;
    asm("mov.b64 {%0, %1}, %2;" : "=f"(r.x), "=f"(r.y) : "l"(v));
    return r;
}
__device__ __forceinline__ float fast_sigmoid(float x)
{
    float e = __expf(-x);
    return __fdividef(1.0f, 1.0f + e);
}
__device__ __forceinline__ float fast_tanh(float x)
{
    /* tanh(x) = 1 - 2/(exp(2x)+1); saturates correctly at +-inf */
    float e = __expf(2.0f * x);
    return 1.0f - __fdividef(2.0f, e + 1.0f);
}

#define FMA4(ROW, WV) { unsigned long long w_ = dupf(WV); \
    fma2(ROW[0], w_, zp0); fma2(ROW[1], w_, zp1);          \
    fma2(ROW[2], w_, zp2); fma2(ROW[3], w_, zp3); }

extern __shared__ float sm[];

__global__ __launch_bounds__(THREADS, 1)
void node_kernel(const float* __restrict__ x0g,
                 const float* __restrict__ h1w, const float* __restrict__ h1b,
                 const float* __restrict__ g1w, const float* __restrict__ g1b,
                 const float* __restrict__ h2b, const float* __restrict__ g2b,
                 const float* __restrict__ outw, const float* __restrict__ outb,
                 float* __restrict__ outg)
{
    const int t = threadIdx.x;

    /* ---- one-time per block: weights into SMEM ---- */
    for (int j = t; j < 2 * 16896; j += THREADS) sm[j] = d_wT[j];
    for (int j = t; j < 512; j += THREADS) {
        sm[OFF_H1W + j] = h1w[j];
        sm[OFF_G1W + j] = g1w[j];
    }
    if (t < 128) {
        sm[OFF_H1B + t] = h1b[t]; sm[OFF_G1B + t] = g1b[t];
        sm[OFF_H2B + t] = h2b[t]; sm[OFF_G2B + t] = g2b[t];
    }
    for (int j = t; j < 384; j += THREADS) sm[OFF_OUTW + j] = outw[j];  /* FIXED: was `if (t<384)` which with 256 threads dropped outw[256..383] */
    if (t < 3)   sm[OFF_OUTB + t] = outb[t];

    const int cg = t & 31, pg = t >> 5;
    const int c0 = cg * 4, p0 = pg * 8;
    const int l1p = t & 63, l1ob = (t >> 6) * 32;
    const int oc = t / 64;      /* out-pass channel (t<192) */
    const int op = t - oc * 64; /* out-pass point           */
    const float third = 1.0f / 3.0f;

    for (int tile = blockIdx.x; tile < NTILES; tile += gridDim.x)
    {
        const int b  = tile / NTILES_PER_B;
        const int n0 = (tile - b * NTILES_PER_B) * PTILE;

        __syncthreads();              /* smem reuse fence from prev tile */
        if (t < 192) {
            int n = n0 + op;
            float v = (n < NPTS) ? x0g[(size_t)b * 3 * NPTS + (size_t)oc * NPTS + n]
                                 : 0.0f;
            sm[OFF_X0 + t] = v;
            sm[OFF_XC + t] = v;
        }
        __syncthreads();

        #pragma unroll
        for (int s = 0; s < 4; ++s)
        {
            const float ts = (s == 0) ? 0.0f : (s == 1) ? third
                           : (s == 2) ? 2.0f * third : 1.0f;

            /* ---------- layer 1: (x,t) -> z1[128][64] ---------- */
            {
                float xa = sm[OFF_XC + l1p];
                float xb = sm[OFF_XC + 64 + l1p];
                float xc = sm[OFF_XC + 128 + l1p];
                #pragma unroll 8
                for (int k = 0; k < 32; ++k) {
                    int o = l1ob + k;
                    float4 hw = *(const float4*)&sm[OFF_H1W + o * 4];
                    float4 gw = *(const float4*)&sm[OFF_G1W + o * 4];
                    float h = sm[OFF_H1B + o] + hw.x * xa + hw.y * xb + hw.z * xc + hw.w * ts;
                    float g = sm[OFF_G1B + o] + gw.x * xa + gw.y * xb + gw.z * xc + gw.w * ts;
                    sm[OFF_Z1 + o * STR + l1p] = fmaxf(h * fast_sigmoid(g), 0.0f);
                }
            }
            __syncthreads();

            /* ---------- layer 2: dual 128x128 GEMM + GLU, f32x2 packed ---------- */
            {
                unsigned long long ha[4][4], ga[4][4];
                {
                    float4 hb4 = *(const float4*)&sm[OFF_H2B + c0];
                    float4 gb4 = *(const float4*)&sm[OFF_G2B + c0];
                    unsigned long long d0 = dupf(hb4.x), d1 = dupf(hb4.y),
                                       d2 = dupf(hb4.z), d3 = dupf(hb4.w);
                    unsigned long long e0 = dupf(gb4.x), e1 = dupf(gb4.y),
                                       e2 = dupf(gb4.z), e3 = dupf(gb4.w);
                    #pragma unroll
                    for (int pp = 0; pp < 4; ++pp) {
                        ha[0][pp] = d0; ha[1][pp] = d1; ha[2][pp] = d2; ha[3][pp] = d3;
                        ga[0][pp] = e0; ga[1][pp] = e1; ga[2][pp] = e2; ga[3][pp] = e3;
                    }
                }
                #pragma unroll 4
                for (int i = 0; i < 128; ++i) {
                    const float* zr = &sm[OFF_Z1 + i * STR + p0];
                    ulonglong2 zA = *(const ulonglong2*)zr;        /* broadcast */
                    ulonglong2 zB = *(const ulonglong2*)(zr + 4);
                    float4 wh4 = *(const float4*)&sm[OFF_H2T + i * WPAD + c0];
                    float4 wg4 = *(const float4*)&sm[OFF_G2T + i * WPAD + c0];
                    unsigned long long zp0 = zA.x, zp1 = zA.y, zp2 = zB.x, zp3 = zB.y;
                    FMA4(ha[0], wh4.x); FMA4(ha[1], wh4.y);
                    FMA4(ha[2], wh4.z); FMA4(ha[3], wh4.w);
                    FMA4(ga[0], wg4.x); FMA4(ga[1], wg4.y);
                    FMA4(ga[2], wg4.z); FMA4(ga[3], wg4.w);
                }
                #pragma unroll
                for (int c = 0; c < 4; ++c) {
                    #pragma unroll
                    for (int pp = 0; pp < 4; ++pp) {
                        float2 hv = unpk(ha[c][pp]);
                        float2 gv = unpk(ga[c][pp]);
                        float2 r;
                        r.x = fmaxf(hv.x * fast_sigmoid(gv.x), 0.0f);
                        r.y = fmaxf(hv.y * fast_sigmoid(gv.y), 0.0f);
                        *(float2*)&sm[OFF_Z2 + (c0 + c) * STR + p0 + pp * 2] = r;
                    }
                }
            }
            __syncthreads();

            /* ---------- out layer + RK4 bookkeeping (192 threads) ---------- */
            if (t < 192) {
                float a0 = 0.f, a1 = 0.f, a2 = 0.f, a3 = 0.f;
                const float* wrow = &sm[OFF_OUTW + oc * 128];
                #pragma unroll 8
                for (int i = 0; i < 128; i += 4) {
                    a0 += wrow[i]     * sm[OFF_Z2 + (i)     * STR + op];
                    a1 += wrow[i + 1] * sm[OFF_Z2 + (i + 1) * STR + op];
                    a2 += wrow[i + 2] * sm[OFF_Z2 + (i + 2) * STR + op];
                    a3 += wrow[i + 3] * sm[OFF_Z2 + (i + 3) * STR + op];
                }
                float v  = sm[OFF_OUTB + oc] + ((a0 + a1) + (a2 + a3));
                float kv = 0.5f * fast_tanh(v);
                float x0v = sm[OFF_X0 + t];
                if (s == 0) {
                    sm[OFF_KS + t] = kv;
                    sm[OFF_K1 + t] = kv;
                    sm[OFF_XC + t] = x0v + kv * third;
                } else if (s == 1) {
                    sm[OFF_KS + t] += 3.0f * kv;
                    sm[OFF_K2 + t] = kv;
                    sm[OFF_XC + t] = x0v + kv - sm[OFF_K1 + t] * third;
                } else if (s == 2) {
                    sm[OFF_KS + t] += 3.0f * kv;
                    sm[OFF_XC + t] = x0v + sm[OFF_K1 + t] - sm[OFF_K2 + t] + kv;
                } else {
                    float y = x0v + 0.125f * (sm[OFF_KS + t] + kv);
                    int n = n0 + op;
                    if (n < NPTS)
                        outg[(size_t)b * 3 * NPTS + (size_t)oc * NPTS + n] = y;
                }
            }
            __syncthreads();
        } /* stages */
    } /* tiles */
}

extern "C" void kernel_launch(void* const* d_in, const int* in_sizes, int n_in,
                              void* d_out, int out_size)
{
    const float* x0   = (const float*)d_in[0];
    const float* h1w  = (const float*)d_in[1];
    const float* h1b  = (const float*)d_in[2];
    const float* g1w  = (const float*)d_in[3];
    const float* g1b  = (const float*)d_in[4];
    const float* h2w  = (const float*)d_in[5];
    const float* h2b  = (const float*)d_in[6];
    const float* g2w  = (const float*)d_in[7];
    const float* g2b  = (const float*)d_in[8];
    const float* outw = (const float*)d_in[9];
    const float* outb = (const float*)d_in[10];

    cudaFuncSetAttribute(node_kernel,
                         cudaFuncAttributeMaxDynamicSharedMemorySize, SMEM_BYTES);

    wtrans_kernel<<<64, 256>>>(h2w, g2w);
    node_kernel<<<148, THREADS, SMEM_BYTES>>>(x0, h1w, h1b, g1w, g1b,
                                              h2b, g2b, outw, outb,
                                              (float*)d_out);
}

// round 4
// speedup vs baseline: 1.2472x; 1.2472x over previous
#include <cuda_runtime.h>
#include <cuda_bf16.h>

#define NPTS  50000
#define BATCH 8
#define PTILE 64
#define NTILES_PER_B ((NPTS + PTILE - 1) / PTILE)   /* 782 */
#define NTILES (BATCH * NTILES_PER_B)               /* 6256 */
#define THREADS 256
#define GRID 296

/* ---- SMEM word/float offsets (all 4B units, one extern array) ---- */
#define Z1H_W   0        /* z1 hi plane: [64 pt][stride 68 words] bf16x2  */
#define Z1L_W   4352     /* z1 lo plane                                   */
#define Z1STRW  68       /* words per point row (136 bf16)                */
#define Z2F     8704     /* z2 fp32 [64 pt][stride 133]                   */
#define Z2STR   133
#define H1WF    17216
#define G1WF    17728
#define H1BF    18240
#define G1BF    18368
#define H2BF    18496
#define G2BF    18624
#define OUTWF   18752
#define OUTBF   19136
#define X0F     19140
#define XCF     19332
#define K1F     19524
#define K2F     19716
#define KSF     19908
#define SMEM_FLOATS 20100
#define SMEM_BYTES  (SMEM_FLOATS * 4)

/* A fragments, built by prep kernel:
   [gemm(2:h,g)][plane(2:hi,lo)][mstrip(8)][kstep(8)][lane(32)] int4 */
__device__ int4 d_Afrag[8192];

__device__ __forceinline__ unsigned bfpack(float v0, float v1) {
    __nv_bfloat16 b0 = __float2bfloat16_rn(v0);
    __nv_bfloat16 b1 = __float2bfloat16_rn(v1);
    return (unsigned)__bfloat16_as_ushort(b0)
         | ((unsigned)__bfloat16_as_ushort(b1) << 16);
}
__device__ __forceinline__ float bflo(float v) {   /* residual after bf16 round */
    __nv_bfloat16 b = __float2bfloat16_rn(v);
    return v - __bfloat162float(b);
}
__device__ __forceinline__ float fast_sigmoid(float x) {
    float e = __expf(-x);
    return __fdividef(1.0f, 1.0f + e);
}
__device__ __forceinline__ float fast_tanh(float x) {
    float e = __expf(2.0f * x);
    return 1.0f - __fdividef(2.0f, e + 1.0f);
}
__device__ __forceinline__ void mma16816(float* d, const int4 a,
                                         unsigned b0, unsigned b1) {
    asm volatile(
        "mma.sync.aligned.m16n8k16.row.col.f32.bf16.bf16.f32 "
        "{%0,%1,%2,%3}, {%4,%5,%6,%7}, {%8,%9}, {%0,%1,%2,%3};"
        : "+f"(d[0]), "+f"(d[1]), "+f"(d[2]), "+f"(d[3])
        : "r"(a.x), "r"(a.y), "r"(a.z), "r"(a.w), "r"(b0), "r"(b1));
}

/* ---------- prep: per-lane A fragments (hi/lo bf16) from h2_w/g2_w ---------- */
__global__ void prep_kernel(const float* __restrict__ h2w,
                            const float* __restrict__ g2w)
{
    int j = blockIdx.x * blockDim.x + threadIdx.x;
    if (j >= 8192) return;
    int lane  = j & 31;
    int k     = (j >> 5) & 7;
    int m     = (j >> 8) & 7;
    int plane = (j >> 11) & 1;
    int gemm  = (j >> 12) & 1;
    int g = lane >> 2, tq = lane & 3;
    int r0 = m * 16 + g, r1 = r0 + 8;
    int c0 = k * 16 + 2 * tq, c2 = c0 + 8;
    const float* src = gemm ? g2w : h2w;
    float e00 = src[r0 * 128 + c0],     e01 = src[r0 * 128 + c0 + 1];
    float e10 = src[r1 * 128 + c0],     e11 = src[r1 * 128 + c0 + 1];
    float e02 = src[r0 * 128 + c2],     e03 = src[r0 * 128 + c2 + 1];
    float e12 = src[r1 * 128 + c2],     e13 = src[r1 * 128 + c2 + 1];
    if (plane) {  /* lo residual plane */
        e00 = bflo(e00); e01 = bflo(e01); e10 = bflo(e10); e11 = bflo(e11);
        e02 = bflo(e02); e03 = bflo(e03); e12 = bflo(e12); e13 = bflo(e13);
    }
    int4 f;
    f.x = (int)bfpack(e00, e01);
    f.y = (int)bfpack(e10, e11);
    f.z = (int)bfpack(e02, e03);
    f.w = (int)bfpack(e12, e13);
    d_Afrag[j] = f;
}

extern __shared__ float smf[];

__global__ __launch_bounds__(THREADS, 2)
void node_kernel(const float* __restrict__ x0g,
                 const float* __restrict__ h1w, const float* __restrict__ h1b,
                 const float* __restrict__ g1w, const float* __restrict__ g1b,
                 const float* __restrict__ h2b, const float* __restrict__ g2b,
                 const float* __restrict__ outw, const float* __restrict__ outb,
                 float* __restrict__ outg)
{
    const int t = threadIdx.x;
    const int wid = t >> 5, lane = t & 31;
    unsigned* smw = (unsigned*)smf;

    /* ---- one-time small weights into SMEM ---- */
    for (int j = t; j < 512; j += THREADS) {
        smf[H1WF + j] = h1w[j];
        smf[G1WF + j] = g1w[j];
    }
    if (t < 128) {
        smf[H1BF + t] = h1b[t]; smf[G1BF + t] = g1b[t];
        smf[H2BF + t] = h2b[t]; smf[G2BF + t] = g2b[t];
    }
    for (int j = t; j < 384; j += THREADS) smf[OUTWF + j] = outw[j];
    if (t < 3) smf[OUTBF + t] = outb[t];

    /* per-warp GEMM constants */
    const int m  = wid;                 /* m-strip 0..7 (16 ch each) */
    const int g  = lane >> 2, tq = lane & 3;
    const int4* Ahh = d_Afrag + ((0 * 16 + 0 * 8 + m) * 8) * 32 + lane; /* h hi */
    const int4* Ahl = d_Afrag + ((0 * 16 + 1 * 8 + m) * 8) * 32 + lane; /* h lo */
    const int4* Agh = d_Afrag + ((1 * 16 + 0 * 8 + m) * 8) * 32 + lane; /* g hi */
    const int4* Agl = d_Afrag + ((1 * 16 + 1 * 8 + m) * 8) * 32 + lane; /* g lo */

    /* layer-1 mapping: thread -> (pt, 32-ch chunk) */
    const int l1pt = t >> 2, l1cb = (t & 3) * 32;
    /* out-pass mapping (t<192) */
    const int oc = t / 64, op = t - oc * 64;
    const float third = 1.0f / 3.0f;

    for (int tile = blockIdx.x; tile < NTILES; tile += gridDim.x)
    {
        const int b  = tile / NTILES_PER_B;
        const int n0 = (tile - b * NTILES_PER_B) * PTILE;

        __syncthreads();
        if (t < 192) {
            int n = n0 + op;
            float v = (n < NPTS) ? x0g[(size_t)b * 3 * NPTS + (size_t)oc * NPTS + n]
                                 : 0.0f;
            smf[X0F + t] = v;
            smf[XCF + t] = v;
        }
        __syncthreads();

        #pragma unroll
        for (int s = 0; s < 4; ++s)
        {
            const float ts = (s == 0) ? 0.0f : (s == 1) ? third
                           : (s == 2) ? 2.0f * third : 1.0f;

            /* ---------- layer 1 -> z1 bf16 hi/lo planes, [pt][ch] ---------- */
            {
                float xa = smf[XCF + l1pt];
                float xb = smf[XCF + 64 + l1pt];
                float xc = smf[XCF + 128 + l1pt];
                int wbase = l1pt * Z1STRW + (l1cb >> 1);
                #pragma unroll 4
                for (int jj = 0; jj < 16; ++jj) {
                    float z0, z1v;
                    #pragma unroll
                    for (int q = 0; q < 2; ++q) {
                        int o = l1cb + 2 * jj + q;
                        float4 hw = *(const float4*)&smf[H1WF + o * 4];
                        float4 gw = *(const float4*)&smf[G1WF + o * 4];
                        float h = smf[H1BF + o] + hw.x * xa + hw.y * xb + hw.z * xc + hw.w * ts;
                        float gg = smf[G1BF + o] + gw.x * xa + gw.y * xb + gw.z * xc + gw.w * ts;
                        float z = fmaxf(h * fast_sigmoid(gg), 0.0f);
                        if (q == 0) z0 = z; else z1v = z;
                    }
                    smw[Z1H_W + wbase + jj] = bfpack(z0, z1v);
                    smw[Z1L_W + wbase + jj] = bfpack(bflo(z0), bflo(z1v));
                }
            }
            __syncthreads();

            /* ---------- layer 2: mma.sync bf16 split, per-warp m-strip ---------- */
            {
                float hb0 = smf[H2BF + m * 16 + g], hb8 = smf[H2BF + m * 16 + g + 8];
                float gb0 = smf[G2BF + m * 16 + g], gb8 = smf[G2BF + m * 16 + g + 8];
                #pragma unroll
                for (int n = 0; n < 4; ++n) {
                    const int nb = n * 16;
                    float ha[8] = {0, 0, 0, 0, 0, 0, 0, 0};
                    float ga[8] = {0, 0, 0, 0, 0, 0, 0, 0};
                    #pragma unroll
                    for (int k = 0; k < 8; ++k) {
                        int w0 = (nb + g) * Z1STRW + k * 8 + tq;       /* n8 half 0 */
                        int w1 = w0 + 8 * Z1STRW;                      /* n8 half 1 */
                        unsigned bh00 = smw[Z1H_W + w0], bh01 = smw[Z1H_W + w0 + 4];
                        unsigned bh10 = smw[Z1H_W + w1], bh11 = smw[Z1H_W + w1 + 4];
                        unsigned bl00 = smw[Z1L_W + w0], bl01 = smw[Z1L_W + w0 + 4];
                        unsigned bl10 = smw[Z1L_W + w1], bl11 = smw[Z1L_W + w1 + 4];
                        int4 ah = Ahh[k * 32], al = Ahl[k * 32];
                        int4 bh = Agh[k * 32], bl = Agl[k * 32];
                        mma16816(ha + 0, ah, bh00, bh01);
                        mma16816(ha + 0, ah, bl00, bl01);
                        mma16816(ha + 0, al, bh00, bh01);
                        mma16816(ha + 4, ah, bh10, bh11);
                        mma16816(ha + 4, ah, bl10, bl11);
                        mma16816(ha + 4, al, bh10, bh11);
                        mma16816(ga + 0, bh, bh00, bh01);
                        mma16816(ga + 0, bh, bl00, bl01);
                        mma16816(ga + 0, bl, bh00, bh01);
                        mma16816(ga + 4, bh, bh10, bh11);
                        mma16816(ga + 4, bh, bl10, bl11);
                        mma16816(ga + 4, bl, bh10, bh11);
                    }
                    /* GLU epilogue: d layout (g,2t),(g,2t+1),(g+8,2t),(g+8,2t+1) */
                    #pragma unroll
                    for (int half = 0; half < 2; ++half) {
                        int ptb = nb + half * 8 + 2 * tq;
                        const float* hh = ha + half * 4;
                        const float* gg = ga + half * 4;
                        float v0 = fmaxf((hh[0] + hb0) * fast_sigmoid(gg[0] + gb0), 0.0f);
                        float v1 = fmaxf((hh[1] + hb0) * fast_sigmoid(gg[1] + gb0), 0.0f);
                        float v2 = fmaxf((hh[2] + hb8) * fast_sigmoid(gg[2] + gb8), 0.0f);
                        float v3 = fmaxf((hh[3] + hb8) * fast_sigmoid(gg[3] + gb8), 0.0f);
                        int ch0 = m * 16 + g;
                        smf[Z2F + (ptb)     * Z2STR + ch0]     = v0;
                        smf[Z2F + (ptb + 1) * Z2STR + ch0]     = v1;
                        smf[Z2F + (ptb)     * Z2STR + ch0 + 8] = v2;
                        smf[Z2F + (ptb + 1) * Z2STR + ch0 + 8] = v3;
                    }
                }
            }
            __syncthreads();

            /* ---------- out layer + RK4 (192 threads) ---------- */
            if (t < 192) {
                float a0 = 0.f, a1 = 0.f, a2 = 0.f, a3 = 0.f;
                const float* wrow = &smf[OUTWF + oc * 128];
                const float* zrow = &smf[Z2F + op * Z2STR];
                #pragma unroll 8
                for (int i = 0; i < 128; i += 4) {
                    a0 += wrow[i]     * zrow[i];
                    a1 += wrow[i + 1] * zrow[i + 1];
                    a2 += wrow[i + 2] * zrow[i + 2];
                    a3 += wrow[i + 3] * zrow[i + 3];
                }
                float v  = smf[OUTBF + oc] + ((a0 + a1) + (a2 + a3));
                float kv = 0.5f * fast_tanh(v);
                float x0v = smf[X0F + t];
                if (s == 0) {
                    smf[KSF + t] = kv;
                    smf[K1F + t] = kv;
                    smf[XCF + t] = x0v + kv * third;
                } else if (s == 1) {
                    smf[KSF + t] += 3.0f * kv;
                    smf[K2F + t] = kv;
                    smf[XCF + t] = x0v + kv - smf[K1F + t] * third;
                } else if (s == 2) {
                    smf[KSF + t] += 3.0f * kv;
                    smf[XCF + t] = x0v + smf[K1F + t] - smf[K2F + t] + kv;
                } else {
                    float y = x0v + 0.125f * (smf[KSF + t] + kv);
                    int n = n0 + op;
                    if (n < NPTS)
                        outg[(size_t)b * 3 * NPTS + (size_t)oc * NPTS + n] = y;
                }
            }
            __syncthreads();
        } /* stages */
    } /* tiles */
}

extern "C" void kernel_launch(void* const* d_in, const int* in_sizes, int n_in,
                              void* d_out, int out_size)
{
    const float* x0   = (const float*)d_in[0];
    const float* h1w  = (const float*)d_in[1];
    const float* h1b  = (const float*)d_in[2];
    const float* g1w  = (const float*)d_in[3];
    const float* g1b  = (const float*)d_in[4];
    const float* h2w  = (const float*)d_in[5];
    const float* h2b  = (const float*)d_in[6];
    const float* g2w  = (const float*)d_in[7];
    const float* g2b  = (const float*)d_in[8];
    const float* outw = (const float*)d_in[9];
    const float* outb = (const float*)d_in[10];

    cudaFuncSetAttribute(node_kernel,
                         cudaFuncAttributeMaxDynamicSharedMemorySize, SMEM_BYTES);

    prep_kernel<<<32, 256>>>(h2w, g2w);
    node_kernel<<<GRID, THREADS, SMEM_BYTES>>>(x0, h1w, h1b, g1w, g1b,
                                               h2b, g2b, outw, outb,
                                               (float*)d_out);
}

// round 5
// speedup vs baseline: 3.2635x; 2.6166x over previous
#include <cuda_runtime.h>
#include <cuda_fp16.h>

#define NPTS  50000
#define BATCH 8
#define PTILE 64
#define NTILES_PER_B ((NPTS + PTILE - 1) / PTILE)   /* 782 */
#define NTILES (BATCH * NTILES_PER_B)               /* 6256 */
#define THREADS 256
#define GRID 296

/* ---- SMEM word/float offsets (4B units) ---- */
#define Z1H_W   0        /* z1 hi plane: [64 pt][stride 68 words] fp16x2 */
#define Z1L_W   4352     /* z1 lo plane                                  */
#define Z1STRW  68
#define Z2F     8704     /* z2 fp32 [64 pt][stride 132]                  */
#define Z2STR   132
#define OUTWF   17152
#define H2BF    17536
#define G2BF    17664
#define OUTBF   17792
#define X0F     17796
#define XCF     17988
#define K1F     18180
#define K2F     18372
#define KSF     18564
#define SMEM_FLOATS 18756
#define SMEM_BYTES  (SMEM_FLOATS * 4)

/* A fragments fp16 single plane: [gemm(2)][mstrip(8)][kstep(8)][lane(32)] int4 */
__device__ int4 d_Afrag[4096];

__device__ __forceinline__ unsigned hpack(float a, float b) {
    __half2 h = __floats2half2_rn(a, b);
    return *(unsigned*)&h;
}
__device__ __forceinline__ float hlo(float v) {
    return v - __half2float(__float2half_rn(v));
}
__device__ __forceinline__ float fast_sigmoid(float x) {
    float e = __expf(-x);
    return __fdividef(1.0f, 1.0f + e);
}
__device__ __forceinline__ float fast_tanh(float x) {
    float e = __expf(2.0f * x);
    return 1.0f - __fdividef(2.0f, e + 1.0f);
}
__device__ __forceinline__ void mma16816(float* d, const int4 a,
                                         unsigned b0, unsigned b1) {
    asm volatile(
        "mma.sync.aligned.m16n8k16.row.col.f32.f16.f16.f32 "
        "{%0,%1,%2,%3}, {%4,%5,%6,%7}, {%8,%9}, {%0,%1,%2,%3};"
        : "+f"(d[0]), "+f"(d[1]), "+f"(d[2]), "+f"(d[3])
        : "r"(a.x), "r"(a.y), "r"(a.z), "r"(a.w), "r"(b0), "r"(b1));
}

/* ---------- prep: per-lane fp16 A fragments from h2_w/g2_w ---------- */
__global__ void prep_kernel(const float* __restrict__ h2w,
                            const float* __restrict__ g2w)
{
    int j = blockIdx.x * blockDim.x + threadIdx.x;
    if (j >= 4096) return;
    int lane = j & 31;
    int k    = (j >> 5) & 7;
    int m    = (j >> 8) & 7;
    int gemm = (j >> 11) & 1;
    int g = lane >> 2, tq = lane & 3;
    int r0 = m * 16 + g, r1 = r0 + 8;
    int c0 = k * 16 + 2 * tq, c2 = c0 + 8;
    const float* src = gemm ? g2w : h2w;
    int4 f;
    f.x = (int)hpack(src[r0 * 128 + c0], src[r0 * 128 + c0 + 1]);
    f.y = (int)hpack(src[r1 * 128 + c0], src[r1 * 128 + c0 + 1]);
    f.z = (int)hpack(src[r0 * 128 + c2], src[r0 * 128 + c2 + 1]);
    f.w = (int)hpack(src[r1 * 128 + c2], src[r1 * 128 + c2 + 1]);
    d_Afrag[j] = f;
}

extern __shared__ float smf[];

__global__ __launch_bounds__(THREADS, 2)
void node_kernel(const float* __restrict__ x0g,
                 const float* __restrict__ h1w, const float* __restrict__ h1b,
                 const float* __restrict__ g1w, const float* __restrict__ g1b,
                 const float* __restrict__ h2b, const float* __restrict__ g2b,
                 const float* __restrict__ outw, const float* __restrict__ outb,
                 float* __restrict__ outg)
{
    const int t = threadIdx.x;
    const int wid = t >> 5, lane = t & 31;
    unsigned* smw = (unsigned*)smf;

    /* ---- one-time small weights into SMEM ---- */
    if (t < 128) {
        smf[H2BF + t] = h2b[t];
        smf[G2BF + t] = g2b[t];
    }
    for (int j = t; j < 384; j += THREADS) smf[OUTWF + j] = outw[j];
    if (t < 3) smf[OUTBF + t] = outb[t];

    /* per-warp GEMM constants (m-strip = wid) */
    const int m = wid;
    const int g = lane >> 2, tq = lane & 3;
    const int4* Ah = d_Afrag + ((0 * 8 + m) * 8) * 32 + lane;
    const int4* Ag = d_Afrag + ((1 * 8 + m) * 8) * 32 + lane;

    /* layer-1 mapping: thread -> (channel pair cp, point group pg) */
    const int cp = t & 63, pg = t >> 6;
    const int c0 = 2 * cp;
    /* out-pass mapping (t<192) */
    const int oc = t / 64, op = t - oc * 64;
    const float third = 1.0f / 3.0f;

    for (int tile = blockIdx.x; tile < NTILES; tile += gridDim.x)
    {
        const int b  = tile / NTILES_PER_B;
        const int n0 = (tile - b * NTILES_PER_B) * PTILE;

        __syncthreads();
        if (t < 192) {
            int n = n0 + op;
            float v = (n < NPTS) ? x0g[(size_t)b * 3 * NPTS + (size_t)oc * NPTS + n]
                                 : 0.0f;
            smf[X0F + t] = v;
            smf[XCF + t] = v;
        }
        __syncthreads();

        #pragma unroll
        for (int s = 0; s < 4; ++s)
        {
            const float ts = (s == 0) ? 0.0f : (s == 1) ? third
                           : (s == 2) ? 2.0f * third : 1.0f;

            /* ---------- layer 1: reg weights, 2 ch x 16 pts per thread ---------- */
            {
                float4 hwA = *(const float4*)&h1w[c0 * 4];
                float4 hwB = *(const float4*)&h1w[c0 * 4 + 4];
                float4 gwA = *(const float4*)&g1w[c0 * 4];
                float4 gwB = *(const float4*)&g1w[c0 * 4 + 4];
                float hbA = h1b[c0], hbB = h1b[c0 + 1];
                float gbA = g1b[c0], gbB = g1b[c0 + 1];
                int pt0 = pg * 16;
                #pragma unroll 4
                for (int i = 0; i < 16; ++i) {
                    int pt = pt0 + i;
                    float xa = smf[XCF + pt];
                    float xb = smf[XCF + 64 + pt];
                    float xc = smf[XCF + 128 + pt];
                    float hA = hbA + hwA.x * xa + hwA.y * xb + hwA.z * xc + hwA.w * ts;
                    float gA = gbA + gwA.x * xa + gwA.y * xb + gwA.z * xc + gwA.w * ts;
                    float hB = hbB + hwB.x * xa + hwB.y * xb + hwB.z * xc + hwB.w * ts;
                    float gB = gbB + gwB.x * xa + gwB.y * xb + gwB.z * xc + gwB.w * ts;
                    float z0 = fmaxf(hA * fast_sigmoid(gA), 0.0f);
                    float z1 = fmaxf(hB * fast_sigmoid(gB), 0.0f);
                    int w = pt * Z1STRW + cp;
                    smw[Z1H_W + w] = hpack(z0, z1);
                    smw[Z1L_W + w] = hpack(hlo(z0), hlo(z1));
                }
            }
            __syncthreads();

            /* ---------- layer 2: fp16 mma, W single-plane, Z dual-plane ---------- */
            {
                float ha[4][8], ga[4][8];
                #pragma unroll
                for (int n = 0; n < 4; ++n)
                    #pragma unroll
                    for (int j = 0; j < 8; ++j) { ha[n][j] = 0.f; ga[n][j] = 0.f; }

                #pragma unroll
                for (int k = 0; k < 8; ++k) {
                    int4 a_h = Ah[k * 32];
                    int4 a_g = Ag[k * 32];
                    #pragma unroll
                    for (int n = 0; n < 4; ++n) {
                        int w0 = (n * 16 + g) * Z1STRW + k * 8 + tq;
                        int w1 = w0 + 8 * Z1STRW;
                        unsigned bh00 = smw[Z1H_W + w0], bh01 = smw[Z1H_W + w0 + 4];
                        unsigned bh10 = smw[Z1H_W + w1], bh11 = smw[Z1H_W + w1 + 4];
                        unsigned bl00 = smw[Z1L_W + w0], bl01 = smw[Z1L_W + w0 + 4];
                        unsigned bl10 = smw[Z1L_W + w1], bl11 = smw[Z1L_W + w1 + 4];
                        mma16816(ha[n] + 0, a_h, bh00, bh01);
                        mma16816(ha[n] + 0, a_h, bl00, bl01);
                        mma16816(ha[n] + 4, a_h, bh10, bh11);
                        mma16816(ha[n] + 4, a_h, bl10, bl11);
                        mma16816(ga[n] + 0, a_g, bh00, bh01);
                        mma16816(ga[n] + 0, a_g, bl00, bl01);
                        mma16816(ga[n] + 4, a_g, bh10, bh11);
                        mma16816(ga[n] + 4, a_g, bl10, bl11);
                    }
                }

                /* GLU epilogue -> z2 fp32 [pt][132] */
                float hb0 = smf[H2BF + m * 16 + g], hb8 = smf[H2BF + m * 16 + g + 8];
                float gb0 = smf[G2BF + m * 16 + g], gb8 = smf[G2BF + m * 16 + g + 8];
                int ch0 = m * 16 + g;
                #pragma unroll
                for (int n = 0; n < 4; ++n) {
                    #pragma unroll
                    for (int half = 0; half < 2; ++half) {
                        int ptb = n * 16 + half * 8 + 2 * tq;
                        const float* hh = ha[n] + half * 4;
                        const float* gg = ga[n] + half * 4;
                        float v0 = fmaxf((hh[0] + hb0) * fast_sigmoid(gg[0] + gb0), 0.0f);
                        float v1 = fmaxf((hh[1] + hb0) * fast_sigmoid(gg[1] + gb0), 0.0f);
                        float v2 = fmaxf((hh[2] + hb8) * fast_sigmoid(gg[2] + gb8), 0.0f);
                        float v3 = fmaxf((hh[3] + hb8) * fast_sigmoid(gg[3] + gb8), 0.0f);
                        smf[Z2F + (ptb)     * Z2STR + ch0]     = v0;
                        smf[Z2F + (ptb + 1) * Z2STR + ch0]     = v1;
                        smf[Z2F + (ptb)     * Z2STR + ch0 + 8] = v2;
                        smf[Z2F + (ptb + 1) * Z2STR + ch0 + 8] = v3;
                    }
                }
            }
            __syncthreads();

            /* ---------- out layer (float4) + RK4 (192 threads) ---------- */
            if (t < 192) {
                const float4* wrow = (const float4*)&smf[OUTWF + oc * 128];
                const float4* zrow = (const float4*)&smf[Z2F + op * Z2STR];
                float a0 = 0.f, a1 = 0.f, a2 = 0.f, a3 = 0.f;
                #pragma unroll 8
                for (int i = 0; i < 32; ++i) {
                    float4 w4 = wrow[i];
                    float4 z4 = zrow[i];
                    a0 += w4.x * z4.x;
                    a1 += w4.y * z4.y;
                    a2 += w4.z * z4.z;
                    a3 += w4.w * z4.w;
                }
                float v  = smf[OUTBF + oc] + ((a0 + a1) + (a2 + a3));
                float kv = 0.5f * fast_tanh(v);
                float x0v = smf[X0F + t];
                if (s == 0) {
                    smf[KSF + t] = kv;
                    smf[K1F + t] = kv;
                    smf[XCF + t] = x0v + kv * third;
                } else if (s == 1) {
                    smf[KSF + t] += 3.0f * kv;
                    smf[K2F + t] = kv;
                    smf[XCF + t] = x0v + kv - smf[K1F + t] * third;
                } else if (s == 2) {
                    smf[KSF + t] += 3.0f * kv;
                    smf[XCF + t] = x0v + smf[K1F + t] - smf[K2F + t] + kv;
                } else {
                    float y = x0v + 0.125f * (smf[KSF + t] + kv);
                    int n = n0 + op;
                    if (n < NPTS)
                        outg[(size_t)b * 3 * NPTS + (size_t)oc * NPTS + n] = y;
                }
            }
            __syncthreads();
        } /* stages */
    } /* tiles */
}

extern "C" void kernel_launch(void* const* d_in, const int* in_sizes, int n_in,
                              void* d_out, int out_size)
{
    const float* x0   = (const float*)d_in[0];
    const float* h1w  = (const float*)d_in[1];
    const float* h1b  = (const float*)d_in[2];
    const float* g1w  = (const float*)d_in[3];
    const float* g1b  = (const float*)d_in[4];
    const float* h2w  = (const float*)d_in[5];
    const float* h2b  = (const float*)d_in[6];
    const float* g2w  = (const float*)d_in[7];
    const float* g2b  = (const float*)d_in[8];
    const float* outw = (const float*)d_in[9];
    const float* outb = (const float*)d_in[10];

    cudaFuncSetAttribute(node_kernel,
                         cudaFuncAttributeMaxDynamicSharedMemorySize, SMEM_BYTES);

    prep_kernel<<<16, 256>>>(h2w, g2w);
    node_kernel<<<GRID, THREADS, SMEM_BYTES>>>(x0, h1w, h1b, g1w, g1b,
                                               h2b, g2b, outw, outb,
                                               (float*)d_out);
}